// round 16
// baseline (speedup 1.0000x reference)
#include <cuda_runtime.h>
#include <cuda_bf16.h>
#include <cstdint>

// ---------------- problem constants ----------------
#define B32   32
#define NN    325
#define TT    12
#define DD    128
#define G3    384
#define BATCH 384
#define MTOT  124800
#define HH    8
#define HD    16

// ---------------- scratch ----------
__device__ float g_xw[(size_t)3 * MTOT * G3];
__device__ float g_ys[(size_t)3 * MTOT * DD];
// attention output as bf16 hi/lo tiles (ldmatrix layout): [m-tile][hi/lo][64*136]
__device__ __nv_bfloat16 g_ab[MTOT / 64][2][64 * 136];
// preconverted weights: 10 tiles (gru*3+nt for Wih, 9 = Wout), hi+lo, 128x136 bf16
__device__ __nv_bfloat16 g_wb[10][2][128 * 136];

__device__ __forceinline__ unsigned smem_u32(const void* p) {
    return (unsigned)__cvta_generic_to_shared(p);
}
__device__ __forceinline__ float sigmoidf_(float x) {
    return __fdividef(1.f, 1.f + __expf(-x));
}
__device__ __forceinline__ float tanhf_(float x) {
    return __fdividef(2.f, 1.f + __expf(-2.f * x)) - 1.f;
}
__device__ __forceinline__ void cp_async16(unsigned dst_smem, const void* src_gmem) {
    asm volatile("cp.async.cg.shared.global [%0], [%1], 16;" :: "r"(dst_smem), "l"(src_gmem) : "memory");
}
__device__ __forceinline__ void cp_commit() {
    asm volatile("cp.async.commit_group;" ::: "memory");
}
__device__ __forceinline__ void cp_wait0() {
    asm volatile("cp.async.wait_group 0;" ::: "memory");
}

// ---------------- warp-level tensor core helpers ----------
__device__ __forceinline__ void ldsm4(uint32_t* r, unsigned a) {
    asm volatile("ldmatrix.sync.aligned.m8n8.x4.shared.b16 {%0,%1,%2,%3}, [%4];"
        : "=r"(r[0]), "=r"(r[1]), "=r"(r[2]), "=r"(r[3]) : "r"(a));
}
__device__ __forceinline__ void mma_bf16(float* c, const uint32_t* a, const uint32_t* b) {
    asm volatile("mma.sync.aligned.m16n8k16.row.col.f32.bf16.bf16.f32 "
        "{%0,%1,%2,%3}, {%4,%5,%6,%7}, {%8,%9}, {%0,%1,%2,%3};"
        : "+f"(c[0]), "+f"(c[1]), "+f"(c[2]), "+f"(c[3])
        : "r"(a[0]), "r"(a[1]), "r"(a[2]), "r"(a[3]), "r"(b[0]), "r"(b[1]));
}
__device__ __forceinline__ uint32_t bf16x2_pack(float lo, float hi) {
    uint32_t r;
    asm("cvt.rn.bf16x2.f32 %0, %2, %1;" : "=r"(r) : "f"(lo), "f"(hi));
    return r;
}

#define TILE_A64  (64 * 136 * 2)
#define TILE_B128 (128 * 136 * 2)

__device__ __forceinline__ void convert_rows(const float* __restrict__ S, size_t lds,
                                             int r0, int rows,
                                             uint32_t* H32, uint32_t* L32, int nthr)
{
    int tid = threadIdx.x;
    for (int u = tid; u < rows * 32; u += nthr) {
        int r = u >> 5, c4 = (u & 31) << 2;
        int o = r * 68 + (c4 >> 1);
        float4 f = *(const float4*)(S + (size_t)(r0 + r) * lds + c4);
        float h0 = __bfloat162float(__float2bfloat16(f.x));
        float h1 = __bfloat162float(__float2bfloat16(f.y));
        float h2 = __bfloat162float(__float2bfloat16(f.z));
        float h3 = __bfloat162float(__float2bfloat16(f.w));
        H32[o]     = bf16x2_pack(h0, h1);
        H32[o + 1] = bf16x2_pack(h2, h3);
        L32[o]     = bf16x2_pack(f.x - h0, f.y - h1);
        L32[o + 1] = bf16x2_pack(f.z - h2, f.w - h3);
    }
}

// ========================================================================
// Weight preconvert: 160 blocks, each converts 8 rows of one tile.
// ========================================================================
__global__ void __launch_bounds__(256)
preconv_w(const float* __restrict__ Wq, const float* __restrict__ Wk,
          const float* __restrict__ Wv, const float* __restrict__ Wout)
{
    int t   = blockIdx.x >> 4;     // tile 0..9
    int sub = blockIdx.x & 15;     // 8-row slice
    const float* src;
    if (t < 9) {
        int gru = t / 3, nt = t % 3;
        const float* W = (gru == 0) ? Wq : (gru == 1) ? Wk : Wv;
        src = W + (size_t)nt * 128 * 128;
    } else {
        src = Wout;
    }
    convert_rows(src, 128, sub * 8, 8,
                 (uint32_t*)g_wb[t][0] + sub * 8 * 68,
                 (uint32_t*)g_wb[t][1] + sub * 8 * 68, 256);
}

// ========================================================================
// GEMM core (R13 form: 64-row A tile, 256 threads, 2 CTAs/SM)
// ========================================================================
#define G64_SMEM (2 * TILE_A64 + 2 * TILE_B128)   // 104448

__device__ __forceinline__ void load_b_tiles(unsigned sB, int tile)
{
    const char* src = (const char*)g_wb[tile][0];    // hi then lo contiguous (69632 B)
    int tid = threadIdx.x;
#pragma unroll
    for (int i = 0; i < 17; i++) {
        int u = tid + i * 256;
        cp_async16(sB + u * 16, src + (size_t)u * 16);
    }
}

__device__ __forceinline__ void mma_tile_64(
    unsigned sA, unsigned sBh, unsigned sBl,
    int m0, int ncol0,
    const float* __restrict__ bias,
    float* __restrict__ C, int ldc)
{
    int tid = threadIdx.x;
    int wid = tid >> 5, lane = tid & 31;
    int m0w = (wid & 1) * 32;
    int n0w = (wid >> 1) * 32;

    unsigned aoff[2], boff[2];
#pragma unroll
    for (int mt = 0; mt < 2; mt++)
        aoff[mt] = sA + (m0w + mt * 16 + (lane & 15)) * 272 + ((lane >> 4) << 4);
#pragma unroll
    for (int np = 0; np < 2; np++)
        boff[np] = (n0w + np * 16 + ((lane >> 4) << 3) + (lane & 7)) * 272
                 + (((lane >> 3) & 1) << 4);

    float acc[2][4][4];
#pragma unroll
    for (int mt = 0; mt < 2; mt++)
#pragma unroll
        for (int q = 0; q < 4; q++)
#pragma unroll
            for (int i = 0; i < 4; i++) acc[mt][q][i] = 0.f;

#pragma unroll
    for (int pass = 0; pass < 3; pass++) {
        unsigned ab  = (pass == 2) ? (aoff[0] + TILE_A64) : aoff[0];
        unsigned ab1 = (pass == 2) ? (aoff[1] + TILE_A64) : aoff[1];
        unsigned bb  = (pass == 1) ? sBl : sBh;
#pragma unroll
        for (int ks = 0; ks < 8; ks++) {
            uint32_t a[2][4], b[2][4];
            ldsm4(a[0], ab + ks * 32);
            ldsm4(a[1], ab1 + ks * 32);
            ldsm4(b[0], bb + boff[0] + ks * 32);
            ldsm4(b[1], bb + boff[1] + ks * 32);
#pragma unroll
            for (int mt = 0; mt < 2; mt++) {
                mma_bf16(acc[mt][0], a[mt], &b[0][0]);
                mma_bf16(acc[mt][1], a[mt], &b[0][2]);
                mma_bf16(acc[mt][2], a[mt], &b[1][0]);
                mma_bf16(acc[mt][3], a[mt], &b[1][2]);
            }
        }
    }

    int crow = lane >> 2;
    int ccol = (lane & 3) * 2;
#pragma unroll
    for (int mt = 0; mt < 2; mt++) {
        int row = m0 + m0w + mt * 16 + crow;
#pragma unroll
        for (int q = 0; q < 4; q++) {
            int col = ncol0 + n0w + q * 8 + ccol;
            float2 bv = *(const float2*)(bias + col);
            float2 v0 = make_float2(acc[mt][q][0] + bv.x, acc[mt][q][1] + bv.y);
            float2 v1 = make_float2(acc[mt][q][2] + bv.x, acc[mt][q][3] + bv.y);
            *(float2*)(C + (size_t)row * ldc + col) = v0;
            *(float2*)(C + (size_t)(row + 8) * ldc + col) = v1;
        }
    }
}

__global__ void __launch_bounds__(256, 2)
gemm_in(const float* __restrict__ Xq, const float* __restrict__ Xk, const float* __restrict__ Xv,
        const float* __restrict__ bq, const float* __restrict__ bk, const float* __restrict__ bv)
{
    extern __shared__ char smc[];
    unsigned sA  = smem_u32(smc);
    unsigned sBh = sA + 2 * TILE_A64;
    unsigned sBl = sBh + TILE_B128;

    int gru = blockIdx.y;
    int m0  = blockIdx.x * 64;

    const float* X = (gru == 0) ? Xq : (gru == 1) ? Xk : Xv;
    const float* bias = (gru == 0) ? bq : (gru == 1) ? bk : bv;
    float* C = g_xw + (size_t)gru * MTOT * G3;

    load_b_tiles(sBh, gru * 3);
    convert_rows(X, 128, m0, 64, (uint32_t*)smc, (uint32_t*)(smc + TILE_A64), 256);

    for (int nt = 0; nt < 3; nt++) {
        cp_commit(); cp_wait0();
        __syncthreads();
        mma_tile_64(sA, sBh, sBl, m0, nt * 128, bias, C, G3);
        __syncthreads();
        if (nt < 2) load_b_tiles(sBh, gru * 3 + nt + 1);
    }
}

// output projection: A tiles preconverted by attention (g_ab) -> pure cp.async + mma
__global__ void __launch_bounds__(256, 2)
gemm_out(const float* __restrict__ bout, float* __restrict__ out)
{
    extern __shared__ char smc[];
    unsigned sA  = smem_u32(smc);
    unsigned sBh = sA + 2 * TILE_A64;
    unsigned sBl = sBh + TILE_B128;
    int tile = blockIdx.x;
    int m0 = tile * 64;
    int tid = threadIdx.x;

    const char* asrc = (const char*)g_ab[tile][0];
#pragma unroll
    for (int i = 0; i < 9; i++) {
        int u = tid + i * 256;
        if (u < 2176) cp_async16(sA + u * 16, asrc + (size_t)u * 16);
    }
    load_b_tiles(sBh, 9);
    cp_commit(); cp_wait0();
    __syncthreads();
    mma_tile_64(sA, sBh, sBl, m0, 0, bout, out, 128);
}

// ========================================================================
// GRU scan v16 — R13 structure with (a) raw pre-activation exchange
// (transcendentals moved to balanced region), (b) deferred cp.async wait.
// smem layout (bytes): Wl 0 | HH 104448 | HL 106624 | Hs 108800 |
//   r_s 113152 | z_s 117376 | gn_s 121600 | xw_s 125824 | total 150656
// ========================================================================
#define SC_HH    104448
#define SC_HL    106624
#define SC_HS    108800
#define SC_RS    113152
#define SC_ZS    117376
#define SC_GN    121600
#define SC_XW    125824
#define SC_SMEM  150656
#define XW_STG   (8 * 388)

__global__ void __launch_bounds__(384, 1)
gru_scan_tc(const float* __restrict__ Whh_q, const float* __restrict__ Whh_k,
            const float* __restrict__ Whh_v,
            const float* __restrict__ bhh_q, const float* __restrict__ bhh_k,
            const float* __restrict__ bhh_v)
{
    extern __shared__ char smc[];
    __nv_bfloat16* Wl  = (__nv_bfloat16*)smc;
    __nv_bfloat16* HHb = (__nv_bfloat16*)(smc + SC_HH);
    __nv_bfloat16* HLb = (__nv_bfloat16*)(smc + SC_HL);
    float*         Hs   = (float*)(smc + SC_HS);
    float*         r_s  = (float*)(smc + SC_RS);
    float*         z_s  = (float*)(smc + SC_ZS);
    float*         gn_s = (float*)(smc + SC_GN);
    float*         xw_s = (float*)(smc + SC_XW);

    unsigned sWl = smem_u32(smc);
    unsigned sHH = smem_u32(smc + SC_HH);
    unsigned sHL = smem_u32(smc + SC_HL);
    unsigned sXW = smem_u32(smc + SC_XW);

    int gru = blockIdx.x / 48;
    int bb  = blockIdx.x % 48;
    int i0  = bb * 8;

    const float* Whh = (gru == 0) ? Whh_q : (gru == 1) ? Whh_k : Whh_v;
    const float* bhh = (gru == 0) ? bhh_q : (gru == 1) ? bhh_k : bhh_v;

    int tid = threadIdx.x;
    int wid = tid >> 5;
    int lane = tid & 31;
    int gatew = wid >> 2;

    for (int idx = tid; idx < G3 * DD; idx += 384) {
        int g = idx >> 7, k = idx & 127;
        float w = Whh[idx];
        float wh = __bfloat162float(__float2bfloat16(w));
        Wl[g * 136 + k] = __float2bfloat16(w - wh);
    }
    for (int idx = tid; idx < 8 * 136; idx += 384) {
        HHb[idx] = __float2bfloat16(0.f);
        HLb[idx] = __float2bfloat16(0.f);
        Hs[idx] = 0.f;
    }

    uint32_t wh[2][8][4];
    {
        const float2* W2 = (const float2*)Whh;
        int rb = wid * 32 + (lane >> 2);
#pragma unroll
        for (int mt = 0; mt < 2; mt++) {
            int r0 = rb + mt * 16;
#pragma unroll
            for (int kt = 0; kt < 8; kt++) {
                int c = kt * 16 + (lane & 3) * 2;
                float2 w00 = W2[(r0 * 128 + c) >> 1];
                float2 w10 = W2[((r0 + 8) * 128 + c) >> 1];
                float2 w01 = W2[(r0 * 128 + c + 8) >> 1];
                float2 w11 = W2[((r0 + 8) * 128 + c + 8) >> 1];
                wh[mt][kt][0] = bf16x2_pack(w00.x, w00.y);
                wh[mt][kt][1] = bf16x2_pack(w10.x, w10.y);
                wh[mt][kt][2] = bf16x2_pack(w01.x, w01.y);
                wh[mt][kt][3] = bf16x2_pack(w11.x, w11.y);
            }
        }
    }

    float bhh_r[4];
#pragma unroll
    for (int k = 0; k < 4; k++) bhh_r[k] = bhh[wid * 32 + (lane >> 2) + 8 * k];

    unsigned aW[2];
#pragma unroll
    for (int mt = 0; mt < 2; mt++)
        aW[mt] = sWl + (wid * 32 + mt * 16 + (lane & 15)) * 272 + ((lane >> 4) << 4);
    unsigned bO = (lane & 7) * 272 + (((lane >> 3) & 1) << 4) + ((lane >> 4) << 5);

    const size_t xwbase = (size_t)(gru * BATCH + i0) * NN * G3;
    const size_t bstride = (size_t)NN * G3;

    {
#pragma unroll
        for (int w2 = 0; w2 < 2; w2++) {
            int c = tid + w2 * 384;
            int b = c / 96, q = c % 96;
            cp_async16(sXW + b * 1552 + q * 16,
                       g_xw + xwbase + (size_t)b * bstride + q * 4);
        }
        cp_commit(); cp_wait0();
    }
    __syncthreads();

    for (int j = 0; j < NN; j++) {
        bool has_next = (j + 1 < NN);
        if (has_next) {
            unsigned dst = sXW + ((j + 1) & 1) * (XW_STG * 4);
#pragma unroll
            for (int w2 = 0; w2 < 2; w2++) {
                int c = tid + w2 * 384;
                int b = c / 96, q = c % 96;
                cp_async16(dst + b * 1552 + q * 16,
                           g_xw + xwbase + (size_t)b * bstride + (size_t)(j + 1) * G3 + q * 4);
            }
            cp_commit();
        }

        uint32_t bh[8][2], bl[8][2];
#pragma unroll
        for (int kp = 0; kp < 4; kp++) {
            uint32_t r[4];
            ldsm4(r, sHH + bO + kp * 64);
            bh[2 * kp][0] = r[0]; bh[2 * kp][1] = r[1];
            bh[2 * kp + 1][0] = r[2]; bh[2 * kp + 1][1] = r[3];
            ldsm4(r, sHL + bO + kp * 64);
            bl[2 * kp][0] = r[0]; bl[2 * kp][1] = r[1];
            bl[2 * kp + 1][0] = r[2]; bl[2 * kp + 1][1] = r[3];
        }

        float cP[2][4], cQ[2][4];
#pragma unroll
        for (int mt = 0; mt < 2; mt++)
#pragma unroll
            for (int i = 0; i < 4; i++) { cP[mt][i] = 0.f; cQ[mt][i] = 0.f; }

#pragma unroll
        for (int kt = 0; kt < 8; kt++) {
            mma_bf16(cP[0], wh[0][kt], bh[kt]);
            mma_bf16(cP[1], wh[1][kt], bh[kt]);
            mma_bf16(cQ[0], wh[0][kt], bl[kt]);
            mma_bf16(cQ[1], wh[1][kt], bl[kt]);
        }
#pragma unroll
        for (int mt = 0; mt < 2; mt++) {
#pragma unroll
            for (int kt = 0; kt < 8; kt++) {
                uint32_t wl[4];
                ldsm4(wl, aW[mt] + kt * 32);
                mma_bf16((kt & 1) ? cQ[mt] : cP[mt], wl, bh[kt]);
            }
        }

        // ---- frag-owner epilogue: exchange RAW pre-activations
        const float* xwc = xw_s + (j & 1) * XW_STG;
        int b0 = 2 * (lane & 3);
#pragma unroll
        for (int mt = 0; mt < 2; mt++) {
            int gg = wid * 32 + mt * 16 + (lane >> 2);
            int e  = gg & 127;
            float s0 = cP[mt][0] + cQ[mt][0];
            float s1 = cP[mt][1] + cQ[mt][1];
            float s2 = cP[mt][2] + cQ[mt][2];
            float s3 = cP[mt][3] + cQ[mt][3];
            if (gatew < 2) {
                float* dst = (gatew == 0) ? r_s : z_s;
                dst[b0 * 132 + e]           = xwc[b0 * 388 + gg]           + s0 + bhh_r[2 * mt];
                dst[(b0 + 1) * 132 + e]     = xwc[(b0 + 1) * 388 + gg]     + s1 + bhh_r[2 * mt];
                dst[b0 * 132 + e + 8]       = xwc[b0 * 388 + gg + 8]       + s2 + bhh_r[2 * mt + 1];
                dst[(b0 + 1) * 132 + e + 8] = xwc[(b0 + 1) * 388 + gg + 8] + s3 + bhh_r[2 * mt + 1];
            } else {
                gn_s[b0 * 132 + e]           = s0 + bhh_r[2 * mt];
                gn_s[(b0 + 1) * 132 + e]     = s1 + bhh_r[2 * mt];
                gn_s[b0 * 132 + e + 8]       = s2 + bhh_r[2 * mt + 1];
                gn_s[(b0 + 1) * 132 + e + 8] = s3 + bhh_r[2 * mt + 1];
            }
        }
        __syncthreads();

        // ---- balanced h-update: all transcendentals here (uniform MUFU load)
        const size_t ybase = ((size_t)(gru * BATCH + i0) * NN + j) * DD;
#pragma unroll
        for (int pp = 0; pp < 3; pp++) {
            int p = tid + pp * 384;
            if (p < 1024) {
                int b = p >> 7, e2 = p & 127;
                float r   = sigmoidf_(r_s[b * 132 + e2]);
                float z   = sigmoidf_(z_s[b * 132 + e2]);
                float ghn = gn_s[b * 132 + e2];
                float xn  = xwc[b * 388 + 256 + e2];
                float hp  = Hs[b * 136 + e2];
                float nn = tanhf_(xn + r * ghn);
                float hnew = (1.f - z) * nn + z * hp;
                Hs[b * 136 + e2] = hnew;
                float hhv = __bfloat162float(__float2bfloat16(hnew));
                HHb[b * 136 + e2] = __float2bfloat16(hnew);
                HLb[b * 136 + e2] = __float2bfloat16(hnew - hhv);
                g_ys[ybase + (size_t)b * (NN * DD) + e2] = hnew;
            }
        }

        cp_wait0();           // retire xw[j+1] now (overlapped the whole step)
        __syncthreads();
    }
}

// ========================================================================
// Attention (R13, unchanged): 192 threads per (b,n); bf16-tile output.
// ========================================================================
__global__ void __launch_bounds__(192)
attn_kernel(const float* __restrict__ rel)
{
    __shared__ float ks[TT * DD];
    __shared__ float vs[TT * DD];

    int b = blockIdx.x / NN;
    int n = blockIdx.x % NN;
    int tid = threadIdx.x;
    const size_t GS = (size_t)MTOT * DD;

    for (int u = tid; u < TT * DD / 4; u += 192) {
        int s = u >> 5, c4 = u & 31;
        size_t base = ((size_t)(b * TT + s) * NN + n) * DD + c4 * 4;
        ((float4*)ks)[u] = *(const float4*)(g_ys + GS + base);
        ((float4*)vs)[u] = *(const float4*)(g_ys + 2 * GS + base);
    }
    __syncthreads();

    int half = tid & 1;
    int k  = tid >> 1;
    int h = k / TT, t = k % TT;
    int d0 = h * HD + half * 8;

    float q[8];
    size_t qb = ((size_t)(b * TT + t) * NN + n) * DD + d0;
    ((float4*)q)[0] = *(const float4*)(g_ys + qb);
    ((float4*)q)[1] = *(const float4*)(g_ys + qb + 4);

    int hbias = (5 * b + n) & 7;
    const float* rp = rel + hbias * TT * TT + t * TT;

    float srow[TT];
#pragma unroll
    for (int s = 0; s < TT; s++) {
        float a = 0.f;
#pragma unroll
        for (int d = 0; d < 8; d++) a += q[d] * ks[s * DD + d0 + d];
        float full = a + __shfl_xor_sync(0xffffffffu, a, 1);
        srow[s] = full * 0.25f + __ldg(&rp[s]);
    }

    float m = srow[0];
#pragma unroll
    for (int s = 1; s < TT; s++) m = fmaxf(m, srow[s]);
    float sum = 0.f;
#pragma unroll
    for (int s = 0; s < TT; s++) { srow[s] = __expf(srow[s] - m); sum += srow[s]; }
    float inv = __fdividef(1.f, sum);

    float o[8];
#pragma unroll
    for (int d = 0; d < 8; d++) o[d] = 0.f;
#pragma unroll
    for (int s = 0; s < TT; s++) {
        float p = srow[s] * inv;
#pragma unroll
        for (int d = 0; d < 8; d++) o[d] += p * vs[s * DD + d0 + d];
    }

    int mrow = (b * NN + n) * TT + t;
    int tile = mrow >> 6;
    int r = mrow & 63;
    uint32_t hi4[4], lo4[4];
#pragma unroll
    for (int i = 0; i < 4; i++) {
        float h0 = __bfloat162float(__float2bfloat16(o[2 * i]));
        float h1 = __bfloat162float(__float2bfloat16(o[2 * i + 1]));
        hi4[i] = bf16x2_pack(h0, h1);
        lo4[i] = bf16x2_pack(o[2 * i] - h0, o[2 * i + 1] - h1);
    }
    int off = r * 136 + d0;
    *(uint4*)((char*)g_ab[tile][0] + off * 2) = make_uint4(hi4[0], hi4[1], hi4[2], hi4[3]);
    *(uint4*)((char*)g_ab[tile][1] + off * 2) = make_uint4(lo4[0], lo4[1], lo4[2], lo4[3]);
}

// ========================================================================
extern "C" void kernel_launch(void* const* d_in, const int* in_sizes, int n_in,
                              void* d_out, int out_size)
{
    const float* query = (const float*)d_in[0];
    const float* key   = (const float*)d_in[1];
    const float* value = (const float*)d_in[2];
    const float* Wih_q = (const float*)d_in[3];
    const float* Whh_q = (const float*)d_in[4];
    const float* bih_q = (const float*)d_in[5];
    const float* bhh_q = (const float*)d_in[6];
    const float* Wih_k = (const float*)d_in[7];
    const float* Whh_k = (const float*)d_in[8];
    const float* bih_k = (const float*)d_in[9];
    const float* bhh_k = (const float*)d_in[10];
    const float* Wih_v = (const float*)d_in[11];
    const float* Whh_v = (const float*)d_in[12];
    const float* bih_v = (const float*)d_in[13];
    const float* bhh_v = (const float*)d_in[14];
    const float* rel   = (const float*)d_in[15];
    const float* Wout  = (const float*)d_in[16];
    const float* bout  = (const float*)d_in[17];

    cudaFuncSetAttribute(gemm_in,     cudaFuncAttributeMaxDynamicSharedMemorySize, G64_SMEM);
    cudaFuncSetAttribute(gemm_out,    cudaFuncAttributeMaxDynamicSharedMemorySize, G64_SMEM);
    cudaFuncSetAttribute(gru_scan_tc, cudaFuncAttributeMaxDynamicSharedMemorySize, SC_SMEM);

    // 0) preconvert all weight matrices (160 fine-grained blocks)
    preconv_w<<<160, 256>>>(Wih_q, Wih_k, Wih_v, Wout);

    // 1) input projections (R13 config: 64-row blocks, 2 CTAs/SM)
    gemm_in<<<dim3(MTOT / 64, 3), 256, G64_SMEM>>>(query, key, value,
                                                   bih_q, bih_k, bih_v);

    // 2) GRU scans
    gru_scan_tc<<<144, 384, SC_SMEM>>>(Whh_q, Whh_k, Whh_v, bhh_q, bhh_k, bhh_v);

    // 3) attentions
    attn_kernel<<<B32 * NN, 192>>>(rel);

    // 4) output projection
    gemm_out<<<MTOT / 64, 256, G64_SMEM>>>(bout, (float*)d_out);
}

// round 17
// speedup vs baseline: 1.0329x; 1.0329x over previous
#include <cuda_runtime.h>
#include <cuda_bf16.h>
#include <cstdint>

// ---------------- problem constants ----------------
#define B32   32
#define NN    325
#define TT    12
#define DD    128
#define G3    384
#define BATCH 384
#define MTOT  124800
#define HH    8
#define HD    16

// ---------------- scratch ----------
__device__ float g_xw[(size_t)3 * MTOT * G3];
__device__ float g_ys[(size_t)3 * MTOT * DD];
// attention output as bf16 hi/lo tiles (ldmatrix layout): [m-tile][hi/lo][64*136]
__device__ __nv_bfloat16 g_ab[MTOT / 64][2][64 * 136];
// preconverted weights: 10 tiles (gru*3+nt for Wih, 9 = Wout), hi+lo, 128x136 bf16
__device__ __nv_bfloat16 g_wb[10][2][128 * 136];

__device__ __forceinline__ unsigned smem_u32(const void* p) {
    return (unsigned)__cvta_generic_to_shared(p);
}
__device__ __forceinline__ float sigmoidf_(float x) {
    return __fdividef(1.f, 1.f + __expf(-x));
}
__device__ __forceinline__ float tanhf_(float x) {
    return __fdividef(2.f, 1.f + __expf(-2.f * x)) - 1.f;
}
__device__ __forceinline__ void cp_async16(unsigned dst_smem, const void* src_gmem) {
    asm volatile("cp.async.cg.shared.global [%0], [%1], 16;" :: "r"(dst_smem), "l"(src_gmem) : "memory");
}
__device__ __forceinline__ void cp_commit() {
    asm volatile("cp.async.commit_group;" ::: "memory");
}
__device__ __forceinline__ void cp_wait0() {
    asm volatile("cp.async.wait_group 0;" ::: "memory");
}

// ---------------- warp-level tensor core helpers ----------
__device__ __forceinline__ void ldsm4(uint32_t* r, unsigned a) {
    asm volatile("ldmatrix.sync.aligned.m8n8.x4.shared.b16 {%0,%1,%2,%3}, [%4];"
        : "=r"(r[0]), "=r"(r[1]), "=r"(r[2]), "=r"(r[3]) : "r"(a));
}
__device__ __forceinline__ void mma_bf16(float* c, const uint32_t* a, const uint32_t* b) {
    asm volatile("mma.sync.aligned.m16n8k16.row.col.f32.bf16.bf16.f32 "
        "{%0,%1,%2,%3}, {%4,%5,%6,%7}, {%8,%9}, {%0,%1,%2,%3};"
        : "+f"(c[0]), "+f"(c[1]), "+f"(c[2]), "+f"(c[3])
        : "r"(a[0]), "r"(a[1]), "r"(a[2]), "r"(a[3]), "r"(b[0]), "r"(b[1]));
}
__device__ __forceinline__ uint32_t bf16x2_pack(float lo, float hi) {
    uint32_t r;
    asm("cvt.rn.bf16x2.f32 %0, %2, %1;" : "=r"(r) : "f"(lo), "f"(hi));
    return r;
}

#define TILE_A64  (64 * 136 * 2)
#define TILE_B128 (128 * 136 * 2)

__device__ __forceinline__ void convert_rows(const float* __restrict__ S, size_t lds,
                                             int r0, int rows,
                                             uint32_t* H32, uint32_t* L32, int nthr)
{
    int tid = threadIdx.x;
    for (int u = tid; u < rows * 32; u += nthr) {
        int r = u >> 5, c4 = (u & 31) << 2;
        int o = r * 68 + (c4 >> 1);
        float4 f = *(const float4*)(S + (size_t)(r0 + r) * lds + c4);
        float h0 = __bfloat162float(__float2bfloat16(f.x));
        float h1 = __bfloat162float(__float2bfloat16(f.y));
        float h2 = __bfloat162float(__float2bfloat16(f.z));
        float h3 = __bfloat162float(__float2bfloat16(f.w));
        H32[o]     = bf16x2_pack(h0, h1);
        H32[o + 1] = bf16x2_pack(h2, h3);
        L32[o]     = bf16x2_pack(f.x - h0, f.y - h1);
        L32[o + 1] = bf16x2_pack(f.z - h2, f.w - h3);
    }
}

// ========================================================================
// Weight preconvert
// ========================================================================
__global__ void __launch_bounds__(256)
preconv_w(const float* __restrict__ Wq, const float* __restrict__ Wk,
          const float* __restrict__ Wv, const float* __restrict__ Wout)
{
    int t = blockIdx.x;
    const float* src;
    if (t < 9) {
        int gru = t / 3, nt = t % 3;
        const float* W = (gru == 0) ? Wq : (gru == 1) ? Wk : Wv;
        src = W + (size_t)nt * 128 * 128;
    } else {
        src = Wout;
    }
    convert_rows(src, 128, 0, 128, (uint32_t*)g_wb[t][0], (uint32_t*)g_wb[t][1], 256);
}

// ========================================================================
// GEMM core: 64-row A tile, 256 threads, 2 CTAs/SM.
// B tiles pre-converted in gmem; loaded via cp.async.
// ========================================================================
#define G64_SMEM (2 * TILE_A64 + 2 * TILE_B128)   // 104448

__device__ __forceinline__ void load_b_tiles(unsigned sB, int tile)
{
    const char* src = (const char*)g_wb[tile][0];    // hi then lo contiguous (69632 B)
    int tid = threadIdx.x;
#pragma unroll
    for (int i = 0; i < 17; i++) {
        int u = tid + i * 256;
        cp_async16(sB + u * 16, src + (size_t)u * 16);
    }
}

__device__ __forceinline__ void mma_tile_64(
    unsigned sA, unsigned sBh, unsigned sBl,
    int m0, int ncol0,
    const float* __restrict__ bias,
    float* __restrict__ C, int ldc)
{
    int tid = threadIdx.x;
    int wid = tid >> 5, lane = tid & 31;
    int m0w = (wid & 1) * 32;
    int n0w = (wid >> 1) * 32;

    unsigned aoff[2], boff[2];
#pragma unroll
    for (int mt = 0; mt < 2; mt++)
        aoff[mt] = sA + (m0w + mt * 16 + (lane & 15)) * 272 + ((lane >> 4) << 4);
#pragma unroll
    for (int np = 0; np < 2; np++)
        boff[np] = (n0w + np * 16 + ((lane >> 4) << 3) + (lane & 7)) * 272
                 + (((lane >> 3) & 1) << 4);

    float acc[2][4][4];
#pragma unroll
    for (int mt = 0; mt < 2; mt++)
#pragma unroll
        for (int q = 0; q < 4; q++)
#pragma unroll
            for (int i = 0; i < 4; i++) acc[mt][q][i] = 0.f;

#pragma unroll
    for (int pass = 0; pass < 3; pass++) {
        unsigned ab  = (pass == 2) ? (aoff[0] + TILE_A64) : aoff[0];
        unsigned ab1 = (pass == 2) ? (aoff[1] + TILE_A64) : aoff[1];
        unsigned bb  = (pass == 1) ? sBl : sBh;
#pragma unroll
        for (int ks = 0; ks < 8; ks++) {
            uint32_t a[2][4], b[2][4];
            ldsm4(a[0], ab + ks * 32);
            ldsm4(a[1], ab1 + ks * 32);
            ldsm4(b[0], bb + boff[0] + ks * 32);
            ldsm4(b[1], bb + boff[1] + ks * 32);
#pragma unroll
            for (int mt = 0; mt < 2; mt++) {
                mma_bf16(acc[mt][0], a[mt], &b[0][0]);
                mma_bf16(acc[mt][1], a[mt], &b[0][2]);
                mma_bf16(acc[mt][2], a[mt], &b[1][0]);
                mma_bf16(acc[mt][3], a[mt], &b[1][2]);
            }
        }
    }

    int crow = lane >> 2;
    int ccol = (lane & 3) * 2;
#pragma unroll
    for (int mt = 0; mt < 2; mt++) {
        int row = m0 + m0w + mt * 16 + crow;
#pragma unroll
        for (int q = 0; q < 4; q++) {
            int col = ncol0 + n0w + q * 8 + ccol;
            float2 bv = *(const float2*)(bias + col);
            float2 v0 = make_float2(acc[mt][q][0] + bv.x, acc[mt][q][1] + bv.y);
            float2 v1 = make_float2(acc[mt][q][2] + bv.x, acc[mt][q][3] + bv.y);
            *(float2*)(C + (size_t)row * ldc + col) = v0;
            *(float2*)(C + (size_t)(row + 8) * ldc + col) = v1;
        }
    }
}

__global__ void __launch_bounds__(256, 2)
gemm_in(const float* __restrict__ Xq, const float* __restrict__ Xk, const float* __restrict__ Xv,
        const float* __restrict__ bq, const float* __restrict__ bk, const float* __restrict__ bv)
{
    extern __shared__ char smc[];
    unsigned sA  = smem_u32(smc);
    unsigned sBh = sA + 2 * TILE_A64;
    unsigned sBl = sBh + TILE_B128;

    int gru = blockIdx.y;
    int m0  = blockIdx.x * 64;

    const float* X = (gru == 0) ? Xq : (gru == 1) ? Xk : Xv;
    const float* bias = (gru == 0) ? bq : (gru == 1) ? bk : bv;
    float* C = g_xw + (size_t)gru * MTOT * G3;

    load_b_tiles(sBh, gru * 3);
    convert_rows(X, 128, m0, 64, (uint32_t*)smc, (uint32_t*)(smc + TILE_A64), 256);

    for (int nt = 0; nt < 3; nt++) {
        cp_commit(); cp_wait0();
        __syncthreads();
        mma_tile_64(sA, sBh, sBl, m0, nt * 128, bias, C, G3);
        __syncthreads();
        if (nt < 2) load_b_tiles(sBh, gru * 3 + nt + 1);
    }
}

// output projection: A tiles preconverted by attention (g_ab) -> pure cp.async + mma
__global__ void __launch_bounds__(256, 2)
gemm_out(const float* __restrict__ bout, float* __restrict__ out)
{
    extern __shared__ char smc[];
    unsigned sA  = smem_u32(smc);
    unsigned sBh = sA + 2 * TILE_A64;
    unsigned sBl = sBh + TILE_B128;
    int tile = blockIdx.x;
    int m0 = tile * 64;
    int tid = threadIdx.x;

    const char* asrc = (const char*)g_ab[tile][0];
#pragma unroll
    for (int i = 0; i < 9; i++) {
        int u = tid + i * 256;
        if (u < 2176) cp_async16(sA + u * 16, asrc + (size_t)u * 16);
    }
    load_b_tiles(sBh, 9);
    cp_commit(); cp_wait0();
    __syncthreads();
    mma_tile_64(sA, sBh, sBl, m0, 0, bout, out, 128);
}

// ========================================================================
// GRU scan (R12/R13 best): frag-owner epilogue + smem-staged xw.
// ========================================================================
#define SC_HH    104448
#define SC_HL    106624
#define SC_HS    108800
#define SC_RS    113152
#define SC_ZS    117376
#define SC_GN    121600
#define SC_XW    125824
#define SC_SMEM  150656
#define XW_STG   (8 * 388)

__global__ void __launch_bounds__(384, 1)
gru_scan_tc(const float* __restrict__ Whh_q, const float* __restrict__ Whh_k,
            const float* __restrict__ Whh_v,
            const float* __restrict__ bhh_q, const float* __restrict__ bhh_k,
            const float* __restrict__ bhh_v)
{
    extern __shared__ char smc[];
    __nv_bfloat16* Wl  = (__nv_bfloat16*)smc;
    __nv_bfloat16* HHb = (__nv_bfloat16*)(smc + SC_HH);
    __nv_bfloat16* HLb = (__nv_bfloat16*)(smc + SC_HL);
    float*         Hs   = (float*)(smc + SC_HS);
    float*         r_s  = (float*)(smc + SC_RS);
    float*         z_s  = (float*)(smc + SC_ZS);
    float*         gn_s = (float*)(smc + SC_GN);
    float*         xw_s = (float*)(smc + SC_XW);

    unsigned sWl = smem_u32(smc);
    unsigned sHH = smem_u32(smc + SC_HH);
    unsigned sHL = smem_u32(smc + SC_HL);
    unsigned sXW = smem_u32(smc + SC_XW);

    int gru = blockIdx.x / 48;
    int bb  = blockIdx.x % 48;
    int i0  = bb * 8;

    const float* Whh = (gru == 0) ? Whh_q : (gru == 1) ? Whh_k : Whh_v;
    const float* bhh = (gru == 0) ? bhh_q : (gru == 1) ? bhh_k : bhh_v;

    int tid = threadIdx.x;
    int wid = tid >> 5;
    int lane = tid & 31;
    int gatew = wid >> 2;      // per-warp gate type: 0=r 1=z 2=n

    for (int idx = tid; idx < G3 * DD; idx += 384) {
        int g = idx >> 7, k = idx & 127;
        float w = Whh[idx];
        float wh = __bfloat162float(__float2bfloat16(w));
        Wl[g * 136 + k] = __float2bfloat16(w - wh);
    }
    for (int idx = tid; idx < 8 * 136; idx += 384) {
        HHb[idx] = __float2bfloat16(0.f);
        HLb[idx] = __float2bfloat16(0.f);
        Hs[idx] = 0.f;
    }

    // Wh a-frags pinned in registers
    uint32_t wh[2][8][4];
    {
        const float2* W2 = (const float2*)Whh;
        int rb = wid * 32 + (lane >> 2);
#pragma unroll
        for (int mt = 0; mt < 2; mt++) {
            int r0 = rb + mt * 16;
#pragma unroll
            for (int kt = 0; kt < 8; kt++) {
                int c = kt * 16 + (lane & 3) * 2;
                float2 w00 = W2[(r0 * 128 + c) >> 1];
                float2 w10 = W2[((r0 + 8) * 128 + c) >> 1];
                float2 w01 = W2[(r0 * 128 + c + 8) >> 1];
                float2 w11 = W2[((r0 + 8) * 128 + c + 8) >> 1];
                wh[mt][kt][0] = bf16x2_pack(w00.x, w00.y);
                wh[mt][kt][1] = bf16x2_pack(w10.x, w10.y);
                wh[mt][kt][2] = bf16x2_pack(w01.x, w01.y);
                wh[mt][kt][3] = bf16x2_pack(w11.x, w11.y);
            }
        }
    }

    float bhh_r[4];
#pragma unroll
    for (int k = 0; k < 4; k++) bhh_r[k] = bhh[wid * 32 + (lane >> 2) + 8 * k];

    unsigned aW[2];
#pragma unroll
    for (int mt = 0; mt < 2; mt++)
        aW[mt] = sWl + (wid * 32 + mt * 16 + (lane & 15)) * 272 + ((lane >> 4) << 4);
    unsigned bO = (lane & 7) * 272 + (((lane >> 3) & 1) << 4) + ((lane >> 4) << 5);

    const size_t xwbase = (size_t)(gru * BATCH + i0) * NN * G3;
    const size_t bstride = (size_t)NN * G3;

    {
#pragma unroll
        for (int w2 = 0; w2 < 2; w2++) {
            int c = tid + w2 * 384;
            int b = c / 96, q = c % 96;
            cp_async16(sXW + b * 1552 + q * 16,
                       g_xw + xwbase + (size_t)b * bstride + q * 4);
        }
        cp_commit(); cp_wait0();
    }
    __syncthreads();

    for (int j = 0; j < NN; j++) {
        bool has_next = (j + 1 < NN);
        if (has_next) {
            unsigned dst = sXW + ((j + 1) & 1) * (XW_STG * 4);
#pragma unroll
            for (int w2 = 0; w2 < 2; w2++) {
                int c = tid + w2 * 384;
                int b = c / 96, q = c % 96;
                cp_async16(dst + b * 1552 + q * 16,
                           g_xw + xwbase + (size_t)b * bstride + (size_t)(j + 1) * G3 + q * 4);
            }
            cp_commit();
        }

        uint32_t bh[8][2], bl[8][2];
#pragma unroll
        for (int kp = 0; kp < 4; kp++) {
            uint32_t r[4];
            ldsm4(r, sHH + bO + kp * 64);
            bh[2 * kp][0] = r[0]; bh[2 * kp][1] = r[1];
            bh[2 * kp + 1][0] = r[2]; bh[2 * kp + 1][1] = r[3];
            ldsm4(r, sHL + bO + kp * 64);
            bl[2 * kp][0] = r[0]; bl[2 * kp][1] = r[1];
            bl[2 * kp + 1][0] = r[2]; bl[2 * kp + 1][1] = r[3];
        }

        float cP[2][4], cQ[2][4];
#pragma unroll
        for (int mt = 0; mt < 2; mt++)
#pragma unroll
            for (int i = 0; i < 4; i++) { cP[mt][i] = 0.f; cQ[mt][i] = 0.f; }

#pragma unroll
        for (int kt = 0; kt < 8; kt++) {
            mma_bf16(cP[0], wh[0][kt], bh[kt]);
            mma_bf16(cP[1], wh[1][kt], bh[kt]);
            mma_bf16(cQ[0], wh[0][kt], bl[kt]);
            mma_bf16(cQ[1], wh[1][kt], bl[kt]);
        }
#pragma unroll
        for (int mt = 0; mt < 2; mt++) {
#pragma unroll
            for (int kt = 0; kt < 8; kt++) {
                uint32_t wl[4];
                ldsm4(wl, aW[mt] + kt * 32);
                mma_bf16((kt & 1) ? cQ[mt] : cP[mt], wl, bh[kt]);
            }
        }

        // ---- frag-owner epilogue (per-warp uniform gate type)
        const float* xwc = xw_s + (j & 1) * XW_STG;
        int b0 = 2 * (lane & 3);
#pragma unroll
        for (int mt = 0; mt < 2; mt++) {
            int gg = wid * 32 + mt * 16 + (lane >> 2);
            int e  = gg & 127;
            float s0 = cP[mt][0] + cQ[mt][0];
            float s1 = cP[mt][1] + cQ[mt][1];
            float s2 = cP[mt][2] + cQ[mt][2];
            float s3 = cP[mt][3] + cQ[mt][3];
            if (gatew < 2) {
                float* dst = (gatew == 0) ? r_s : z_s;
                float p00 = xwc[b0 * 388 + gg]           + s0 + bhh_r[2 * mt];
                float p01 = xwc[(b0 + 1) * 388 + gg]     + s1 + bhh_r[2 * mt];
                float p10 = xwc[b0 * 388 + gg + 8]       + s2 + bhh_r[2 * mt + 1];
                float p11 = xwc[(b0 + 1) * 388 + gg + 8] + s3 + bhh_r[2 * mt + 1];
                dst[b0 * 132 + e]           = sigmoidf_(p00);
                dst[(b0 + 1) * 132 + e]     = sigmoidf_(p01);
                dst[b0 * 132 + e + 8]       = sigmoidf_(p10);
                dst[(b0 + 1) * 132 + e + 8] = sigmoidf_(p11);
            } else {
                gn_s[b0 * 132 + e]           = s0 + bhh_r[2 * mt];
                gn_s[(b0 + 1) * 132 + e]     = s1 + bhh_r[2 * mt];
                gn_s[b0 * 132 + e + 8]       = s2 + bhh_r[2 * mt + 1];
                gn_s[(b0 + 1) * 132 + e + 8] = s3 + bhh_r[2 * mt + 1];
            }
        }

        cp_wait0();           // retire xw[j+1] before the barrier
        __syncthreads();

        // ---- balanced h-update: 1024 (b,e) pairs over 384 threads
        const size_t ybase = ((size_t)(gru * BATCH + i0) * NN + j) * DD;
#pragma unroll
        for (int pp = 0; pp < 3; pp++) {
            int p = tid + pp * 384;
            if (p < 1024) {
                int b = p >> 7, e2 = p & 127;
                float r   = r_s[b * 132 + e2];
                float z   = z_s[b * 132 + e2];
                float ghn = gn_s[b * 132 + e2];
                float xn  = xwc[b * 388 + 256 + e2];
                float hp  = Hs[b * 136 + e2];
                float nn = tanhf_(xn + r * ghn);
                float hnew = (1.f - z) * nn + z * hp;
                Hs[b * 136 + e2] = hnew;
                float hhv = __bfloat162float(__float2bfloat16(hnew));
                HHb[b * 136 + e2] = __float2bfloat16(hnew);
                HLb[b * 136 + e2] = __float2bfloat16(hnew - hhv);
                g_ys[ybase + (size_t)b * (NN * DD) + e2] = hnew;
            }
        }
        __syncthreads();
    }
}

// ========================================================================
// Attention (R13 best): 192 threads per (b,n); bf16-tile output.
// Bias head index = (5*b + n) mod 8 (replica of the scrambled reshape).
// ========================================================================
__global__ void __launch_bounds__(192)
attn_kernel(const float* __restrict__ rel)
{
    __shared__ float ks[TT * DD];
    __shared__ float vs[TT * DD];

    int b = blockIdx.x / NN;
    int n = blockIdx.x % NN;
    int tid = threadIdx.x;
    const size_t GS = (size_t)MTOT * DD;

    for (int u = tid; u < TT * DD / 4; u += 192) {
        int s = u >> 5, c4 = u & 31;
        size_t base = ((size_t)(b * TT + s) * NN + n) * DD + c4 * 4;
        ((float4*)ks)[u] = *(const float4*)(g_ys + GS + base);
        ((float4*)vs)[u] = *(const float4*)(g_ys + 2 * GS + base);
    }
    __syncthreads();

    int half = tid & 1;
    int k  = tid >> 1;
    int h = k / TT, t = k % TT;
    int d0 = h * HD + half * 8;

    float q[8];
    size_t qb = ((size_t)(b * TT + t) * NN + n) * DD + d0;
    ((float4*)q)[0] = *(const float4*)(g_ys + qb);
    ((float4*)q)[1] = *(const float4*)(g_ys + qb + 4);

    int hbias = (5 * b + n) & 7;
    const float* rp = rel + hbias * TT * TT + t * TT;

    float srow[TT];
#pragma unroll
    for (int s = 0; s < TT; s++) {
        float a = 0.f;
#pragma unroll
        for (int d = 0; d < 8; d++) a += q[d] * ks[s * DD + d0 + d];
        float full = a + __shfl_xor_sync(0xffffffffu, a, 1);
        srow[s] = full * 0.25f + __ldg(&rp[s]);
    }

    float m = srow[0];
#pragma unroll
    for (int s = 1; s < TT; s++) m = fmaxf(m, srow[s]);
    float sum = 0.f;
#pragma unroll
    for (int s = 0; s < TT; s++) { srow[s] = __expf(srow[s] - m); sum += srow[s]; }
    float inv = __fdividef(1.f, sum);

    float o[8];
#pragma unroll
    for (int d = 0; d < 8; d++) o[d] = 0.f;
#pragma unroll
    for (int s = 0; s < TT; s++) {
        float p = srow[s] * inv;
#pragma unroll
        for (int d = 0; d < 8; d++) o[d] += p * vs[s * DD + d0 + d];
    }

    int mrow = (b * NN + n) * TT + t;
    int tile = mrow >> 6;
    int r = mrow & 63;
    uint32_t hi4[4], lo4[4];
#pragma unroll
    for (int i = 0; i < 4; i++) {
        float h0 = __bfloat162float(__float2bfloat16(o[2 * i]));
        float h1 = __bfloat162float(__float2bfloat16(o[2 * i + 1]));
        hi4[i] = bf16x2_pack(h0, h1);
        lo4[i] = bf16x2_pack(o[2 * i] - h0, o[2 * i + 1] - h1);
    }
    int off = r * 136 + d0;
    *(uint4*)((char*)g_ab[tile][0] + off * 2) = make_uint4(hi4[0], hi4[1], hi4[2], hi4[3]);
    *(uint4*)((char*)g_ab[tile][1] + off * 2) = make_uint4(lo4[0], lo4[1], lo4[2], lo4[3]);
}

// ========================================================================
extern "C" void kernel_launch(void* const* d_in, const int* in_sizes, int n_in,
                              void* d_out, int out_size)
{
    const float* query = (const float*)d_in[0];
    const float* key   = (const float*)d_in[1];
    const float* value = (const float*)d_in[2];
    const float* Wih_q = (const float*)d_in[3];
    const float* Whh_q = (const float*)d_in[4];
    const float* bih_q = (const float*)d_in[5];
    const float* bhh_q = (const float*)d_in[6];
    const float* Wih_k = (const float*)d_in[7];
    const float* Whh_k = (const float*)d_in[8];
    const float* bih_k = (const float*)d_in[9];
    const float* bhh_k = (const float*)d_in[10];
    const float* Wih_v = (const float*)d_in[11];
    const float* Whh_v = (const float*)d_in[12];
    const float* bih_v = (const float*)d_in[13];
    const float* bhh_v = (const float*)d_in[14];
    const float* rel   = (const float*)d_in[15];
    const float* Wout  = (const float*)d_in[16];
    const float* bout  = (const float*)d_in[17];

    cudaFuncSetAttribute(gemm_in,     cudaFuncAttributeMaxDynamicSharedMemorySize, G64_SMEM);
    cudaFuncSetAttribute(gemm_out,    cudaFuncAttributeMaxDynamicSharedMemorySize, G64_SMEM);
    cudaFuncSetAttribute(gru_scan_tc, cudaFuncAttributeMaxDynamicSharedMemorySize, SC_SMEM);

    // 0) preconvert all weight matrices to bf16 hi/lo tiles
    preconv_w<<<10, 256>>>(Wih_q, Wih_k, Wih_v, Wout);

    // 1) input projections (64-row blocks, 2 CTAs/SM, preconverted B)
    gemm_in<<<dim3(MTOT / 64, 3), 256, G64_SMEM>>>(query, key, value,
                                                   bih_q, bih_k, bih_v);

    // 2) GRU scans — recurrence on tensor cores
    gru_scan_tc<<<144, 384, SC_SMEM>>>(Whh_q, Whh_k, Whh_v, bhh_q, bhh_k, bhh_v);

    // 3) attentions (one pair per 192-thread block; writes bf16 tiles)
    attn_kernel<<<B32 * NN, 192>>>(rel);

    // 4) output projection (pure cp.async + mma)
    gemm_out<<<MTOT / 64, 256, G64_SMEM>>>(bout, (float*)d_out);
}